// round 1
// baseline (speedup 1.0000x reference)
#include <cuda_runtime.h>
#include <cstdint>
#include <cstddef>

// Problem constants
#define T_STEPS 64
#define NROWS   8192
#define HDIM    256
#define FDIM    256
#define RTILE   64                 // rows per CTA
#define NCTA    (NROWS / RTILE)    // 128
#define NTHR    256
#define KKT     32                 // W k-tile rows
#define KTOT    512                // F + H

// Scratch: concatenated transposed weights [k][j] (k<256: W_ih^T, k>=256: W_hh^T)
__device__ float g_Wt[KTOT * HDIM];
__device__ float g_bias[HDIM];

__global__ void prep_kernel(const float* __restrict__ W_ih,
                            const float* __restrict__ W_hh,
                            const float* __restrict__ b_ih,
                            const float* __restrict__ b_hh) {
    int idx = blockIdx.x * blockDim.x + threadIdx.x;
    if (idx < KTOT * HDIM) {
        int k = idx >> 8;     // 0..511
        int j = idx & 255;
        g_Wt[idx] = (k < 256) ? W_ih[j * 256 + k] : W_hh[j * 256 + (k - 256)];
    }
    if (idx < HDIM) g_bias[idx] = b_ih[idx] + b_hh[idx];
}

// Swizzled offset of the float4 block (k, r=4*rq..4*rq+3) in a [256][64] k-major tile.
// Element (k,r) lives at k*64 + (((r>>2) ^ ((k>>2)&15)) & 15)*4 + (r&3).
__device__ __forceinline__ int sw4(int k, int rq) {
    return (k << 6) + (((rq ^ (k >> 2)) & 15) << 2);
}

#define CP_COMMIT() asm volatile("cp.async.commit_group;\n" ::: "memory")
#define CP_WAIT1()  asm volatile("cp.async.wait_group 1;\n" ::: "memory")
#define CP_WAIT0()  asm volatile("cp.async.wait_group 0;\n" ::: "memory")

__device__ __forceinline__ void cp16(float* dst_s, const float* src_g) {
    unsigned a = (unsigned)__cvta_generic_to_shared(dst_s);
    asm volatile("cp.async.ca.shared.global [%0], [%1], 16;\n" :: "r"(a), "l"(src_g));
}

// SMEM: A_s[256][64] (X^T, swizzled) | H_s[256][64] (h^T, swizzled) | W_s[2][32][256] | bias/lnw/lnb
#define SMEM_FLOATS (256 * 64 * 2 + 2 * KKT * 256 + 3 * 256)
#define SMEM_BYTES  (SMEM_FLOATS * 4)

__global__ void __launch_bounds__(NTHR, 1)
rnn_fused_kernel(const float* __restrict__ X,
                 const float* __restrict__ lnw,
                 const float* __restrict__ lnb,
                 float* __restrict__ out) {
    extern __shared__ float smem[];
    float* A_s    = smem;                    // 16384
    float* H_s    = A_s + 256 * 64;          // 16384
    float* W_s    = H_s + 256 * 64;          // 16384
    float* bias_s = W_s + 2 * KKT * 256;     // 256
    float* lnw_s  = bias_s + 256;
    float* lnb_s  = lnw_s + 256;

    const int tid  = threadIdx.x;
    const int rq   = tid & 15;     // row quad: rows 4*rq..4*rq+3
    const int cg   = tid >> 4;     // col group: cols 16*cg..16*cg+15
    const int c0   = cg << 4;
    const int row0 = blockIdx.x * RTILE;

    if (tid < 256) {
        bias_s[tid] = g_bias[tid];
        lnw_s[tid]  = lnw[tid];
        lnb_s[tid]  = lnb[tid];
    }
    __syncthreads();

    float bias_r[16];
    #pragma unroll
    for (int j = 0; j < 16; ++j) bias_r[j] = bias_s[c0 + j];

    const int lane = tid & 31;
    const int warp = tid >> 5;
    float lnw_r[8], lnb_r[8];
    #pragma unroll
    for (int jj = 0; jj < 8; ++jj) {
        lnw_r[jj] = lnw_s[(lane << 3) + jj];
        lnb_r[jj] = lnb_s[(lane << 3) + jj];
    }

    const int f4 = tid & 63;   // float4 index within a 256-float row
    const int rb = tid >> 6;   // base row 0..3

    for (int t = 0; t < T_STEPS; ++t) {
        // ---- stage X_t transposed+swizzled into A_s ----
        const float* Xt = X + ((size_t)t * NROWS + row0) * FDIM;
        #pragma unroll
        for (int i = 0; i < 16; ++i) {
            int r = rb + (i << 2);                       // rows 0..63, each once
            float4 v = *reinterpret_cast<const float4*>(Xt + r * FDIM + (f4 << 2));
            int f = f4 << 2;                             // k-row; f>>2 == f4
            int base = (f << 6) + ((((r >> 2) ^ f4) & 15) << 2) + (r & 3);
            A_s[base]       = v.x;
            A_s[base + 64]  = v.y;
            A_s[base + 128] = v.z;
            A_s[base + 192] = v.w;
        }

        float c[4][16];
        #pragma unroll
        for (int i = 0; i < 4; ++i)
            #pragma unroll
            for (int j = 0; j < 16; ++j) c[i][j] = 0.0f;

        // ---- W pipeline prologue: tile 0 -> buf 0 ----
        {
            const float* src = g_Wt;
            #pragma unroll
            for (int q = 0; q < 8; ++q) {
                int idx = tid + q * 256;                 // float4 index 0..2047
                cp16(W_s + idx * 4, src + idx * 4);
            }
            CP_COMMIT();
        }

        for (int tile = 0; tile < 16; ++tile) {
            if (tile < 15) {
                const float* src = g_Wt + (tile + 1) * (KKT * 256);
                float* dst = W_s + ((tile + 1) & 1) * (KKT * 256);
                #pragma unroll
                for (int q = 0; q < 8; ++q) {
                    int idx = tid + q * 256;
                    cp16(dst + idx * 4, src + idx * 4);
                }
                CP_COMMIT();
                CP_WAIT1();
            } else {
                CP_WAIT0();
            }
            __syncthreads();

            // t==0: after the X half (tiles 0..7), h0 = Xw0 + b_ih + b_hh (no relu)
            if (t == 0 && tile == 8) {
                #pragma unroll
                for (int j = 0; j < 16; ++j) {
                    float4 hv;
                    hv.x = c[0][j] + bias_r[j];
                    hv.y = c[1][j] + bias_r[j];
                    hv.z = c[2][j] + bias_r[j];
                    hv.w = c[3][j] + bias_r[j];
                    *reinterpret_cast<float4*>(H_s + sw4(c0 + j, rq)) = hv;
                }
                __syncthreads();
            }

            const float* Asrc = (tile < 8) ? A_s : H_s;
            const int    kb   = (tile & 7) * KKT;
            const float* Wt   = W_s + (tile & 1) * (KKT * 256);

            #pragma unroll 4
            for (int kk = 0; kk < KKT; ++kk) {
                int k = kb + kk;
                float4 a  = *reinterpret_cast<const float4*>(Asrc + sw4(k, rq));
                const float* wrow = Wt + kk * 256 + c0;
                float4 b0 = *reinterpret_cast<const float4*>(wrow);
                float4 b1 = *reinterpret_cast<const float4*>(wrow + 4);
                float4 b2 = *reinterpret_cast<const float4*>(wrow + 8);
                float4 b3 = *reinterpret_cast<const float4*>(wrow + 12);
                float av[4]  = {a.x, a.y, a.z, a.w};
                float bv[16] = {b0.x, b0.y, b0.z, b0.w, b1.x, b1.y, b1.z, b1.w,
                                b2.x, b2.y, b2.z, b2.w, b3.x, b3.y, b3.z, b3.w};
                #pragma unroll
                for (int i = 0; i < 4; ++i)
                    #pragma unroll
                    for (int j = 0; j < 16; ++j)
                        c[i][j] = fmaf(av[i], bv[j], c[i][j]);
            }
            __syncthreads();
        }

        // ---- h_new = relu(C + bias); transpose-store into H_s via STS.128 ----
        #pragma unroll
        for (int j = 0; j < 16; ++j) {
            float4 hv;
            hv.x = fmaxf(c[0][j] + bias_r[j], 0.0f);
            hv.y = fmaxf(c[1][j] + bias_r[j], 0.0f);
            hv.z = fmaxf(c[2][j] + bias_r[j], 0.0f);
            hv.w = fmaxf(c[3][j] + bias_r[j], 0.0f);
            *reinterpret_cast<float4*>(H_s + sw4(c0 + j, rq)) = hv;
        }
        __syncthreads();

        // ---- LayerNorm + coalesced output: warp handles rows warp*8 .. warp*8+7 ----
        float* outT = out + ((size_t)t * NROWS + row0) * HDIM;
        #pragma unroll 1
        for (int i = 0; i < 8; ++i) {
            int r = (warp << 3) + i;
            float v[8];
            #pragma unroll
            for (int jj = 0; jj < 8; ++jj) {
                int j = (lane << 3) + jj;
                v[jj] = H_s[(j << 6) + ((((r >> 2) ^ (j >> 2)) & 15) << 2) + (r & 3)];
            }
            float s = 0.0f, s2 = 0.0f;
            #pragma unroll
            for (int jj = 0; jj < 8; ++jj) { s += v[jj]; s2 += v[jj] * v[jj]; }
            #pragma unroll
            for (int o = 16; o > 0; o >>= 1) {
                s  += __shfl_xor_sync(0xffffffffu, s,  o);
                s2 += __shfl_xor_sync(0xffffffffu, s2, o);
            }
            float mean = s  * (1.0f / 256.0f);
            float var  = s2 * (1.0f / 256.0f) - mean * mean;
            float rstd = rsqrtf(var + 1e-5f);
            float o8[8];
            #pragma unroll
            for (int jj = 0; jj < 8; ++jj)
                o8[jj] = (v[jj] - mean) * rstd * lnw_r[jj] + lnb_r[jj];
            float4 w0 = make_float4(o8[0], o8[1], o8[2], o8[3]);
            float4 w1 = make_float4(o8[4], o8[5], o8[6], o8[7]);
            *reinterpret_cast<float4*>(outT + r * HDIM + (lane << 3))     = w0;
            *reinterpret_cast<float4*>(outT + r * HDIM + (lane << 3) + 4) = w1;
        }
        // No trailing sync needed: next step only re-writes A_s / W_s buf0, whose
        // last readers are fenced by the tile-loop barriers above.
    }
}

extern "C" void kernel_launch(void* const* d_in, const int* in_sizes, int n_in,
                              void* d_out, int out_size) {
    const float* X    = (const float*)d_in[0];
    const float* W_ih = (const float*)d_in[1];
    const float* W_hh = (const float*)d_in[2];
    const float* b_ih = (const float*)d_in[3];
    const float* b_hh = (const float*)d_in[4];
    const float* lnw  = (const float*)d_in[5];
    const float* lnb  = (const float*)d_in[6];
    float* out = (float*)d_out;

    (void)in_sizes; (void)n_in; (void)out_size;

    prep_kernel<<<(KTOT * HDIM + 255) / 256, 256>>>(W_ih, W_hh, b_ih, b_hh);

    cudaFuncSetAttribute(rnn_fused_kernel,
                         cudaFuncAttributeMaxDynamicSharedMemorySize, SMEM_BYTES);
    rnn_fused_kernel<<<NCTA, NTHR, SMEM_BYTES>>>(X, lnw, lnb, out);
}

// round 3
// speedup vs baseline: 2.0940x; 2.0940x over previous
#include <cuda_runtime.h>
#include <cuda_bf16.h>
#include <cstdint>
#include <cstddef>

// Problem constants
#define T_STEPS 64
#define NROWS   8192
#define RTILE   64
#define NCTA    (NROWS / RTILE)   // 128
#define NTHR    256

// ---- SMEM layout (bytes) ----
// A_hi : [64 rows][520 bf16]  (512 data + 8 pad)  = 66560 B   @ 0
// A_lo : same                                      = 66560 B   @ 66560
// W_s  : 2 bufs x 32 KB fragment-linear            = 65536 B   @ 133120
// bias / lnw / lnb : 3 x 256 f32                   =  3072 B   @ 198656
#define A_ROW_B   1040         // 520 bf16
#define ALO_OFF   66560
#define W_OFF     133120
#define BIAS_OFF  198656
#define SMEM_BYTES 201728

// W fragments: [chunk16][split2][kt2][ntg32][lane32][word2] uint32 (hi split=0, lo split=1)
__device__ uint32_t g_Wfrag[16 * 2 * 2 * 32 * 32 * 2];   // 131072 words = 512 KB
__device__ float    g_bias[256];

__global__ void prep_kernel(const float* __restrict__ W_ih,
                            const float* __restrict__ W_hh,
                            const float* __restrict__ b_ih,
                            const float* __restrict__ b_hh) {
    int idx = blockIdx.x * blockDim.x + threadIdx.x;
    if (idx < 65536) {
        int w     = idx & 1;
        int lane  = (idx >> 1) & 31;
        int ntg   = (idx >> 6) & 31;
        int kt2   = (idx >> 11) & 1;
        int chunk = idx >> 12;                       // 0..15
        int k = chunk * 32 + kt2 * 16 + (lane & 3) * 2 + w * 8;
        int n = ntg * 8 + (lane >> 2);
        float v0, v1;
        if (k < 256) { v0 = W_ih[n * 256 + k];       v1 = W_ih[n * 256 + k + 1]; }
        else         { v0 = W_hh[n * 256 + k - 256]; v1 = W_hh[n * 256 + k - 255]; }
        __nv_bfloat16 h0 = __float2bfloat16_rn(v0);
        __nv_bfloat16 h1 = __float2bfloat16_rn(v1);
        float r0 = v0 - __bfloat162float(h0);
        float r1 = v1 - __bfloat162float(h1);
        __nv_bfloat162 hiw; hiw.x = h0; hiw.y = h1;
        __nv_bfloat162 low = __floats2bfloat162_rn(r0, r1);
        int base = chunk * 8192 + kt2 * 2048 + ntg * 64 + lane * 2 + w;
        g_Wfrag[base]        = *reinterpret_cast<uint32_t*>(&hiw);   // hi split
        g_Wfrag[base + 4096] = *reinterpret_cast<uint32_t*>(&low);   // lo split
    }
    if (idx < 256) g_bias[idx] = b_ih[idx] + b_hh[idx];
}

// ---- helpers ----
__device__ __forceinline__ uint32_t bf2_hi(float a, float b) {
    __nv_bfloat162 t = __floats2bfloat162_rn(a, b);
    return *reinterpret_cast<uint32_t*>(&t);
}
__device__ __forceinline__ uint32_t bf2_lo(float a, float b) {
    float ra = a - __bfloat162float(__float2bfloat16_rn(a));
    float rb = b - __bfloat162float(__float2bfloat16_rn(b));
    __nv_bfloat162 t = __floats2bfloat162_rn(ra, rb);
    return *reinterpret_cast<uint32_t*>(&t);
}
__device__ __forceinline__ float2 unp_add(uint32_t uh, uint32_t ul) {
    __nv_bfloat162 h = *reinterpret_cast<__nv_bfloat162*>(&uh);
    __nv_bfloat162 l = *reinterpret_cast<__nv_bfloat162*>(&ul);
    float2 r;
    r.x = __bfloat162float(h.x) + __bfloat162float(l.x);
    r.y = __bfloat162float(h.y) + __bfloat162float(l.y);
    return r;
}

#define CP_COMMIT() asm volatile("cp.async.commit_group;\n" ::: "memory")
#define CP_WAIT1()  asm volatile("cp.async.wait_group 1;\n" ::: "memory")
#define CP_WAIT0()  asm volatile("cp.async.wait_group 0;\n" ::: "memory")

__device__ __forceinline__ void cp16(void* dst_s, const void* src_g) {
    unsigned a = (unsigned)__cvta_generic_to_shared(dst_s);
    asm volatile("cp.async.ca.shared.global [%0], [%1], 16;\n" :: "r"(a), "l"(src_g));
}

#define LDSM4(r, addr)                                                          \
    asm volatile("ldmatrix.sync.aligned.m8n8.x4.shared.b16 {%0,%1,%2,%3}, [%4];" \
                 : "=r"((r)[0]), "=r"((r)[1]), "=r"((r)[2]), "=r"((r)[3])        \
                 : "r"(addr))

#define MMA16816(c, a, b0, b1)                                                   \
    asm volatile("mma.sync.aligned.m16n8k16.row.col.f32.bf16.bf16.f32 "          \
                 "{%0,%1,%2,%3}, {%4,%5,%6,%7}, {%8,%9}, {%0,%1,%2,%3};"         \
                 : "+f"((c)[0]), "+f"((c)[1]), "+f"((c)[2]), "+f"((c)[3])        \
                 : "r"((a)[0]), "r"((a)[1]), "r"((a)[2]), "r"((a)[3]),           \
                   "r"(b0), "r"(b1))

// Epilogue: h = (relu?)(C + bias), split to bf16 hi/lo, store into A cols 256..511.
__device__ __forceinline__ void epi_store(float (&c)[2][8][4], const float* bias_s,
                                          char* smem, int wm, int wn, int lane,
                                          bool relu) {
    #pragma unroll
    for (int mt = 0; mt < 2; ++mt) {
        int r = wm * 32 + mt * 16 + (lane >> 2);
        #pragma unroll
        for (int nt = 0; nt < 8; ++nt) {
            int j = wn * 64 + nt * 8 + (lane & 3) * 2;
            float b0 = bias_s[j], b1 = bias_s[j + 1];
            float h00 = c[mt][nt][0] + b0, h01 = c[mt][nt][1] + b1;
            float h10 = c[mt][nt][2] + b0, h11 = c[mt][nt][3] + b1;
            if (relu) {
                h00 = fmaxf(h00, 0.0f); h01 = fmaxf(h01, 0.0f);
                h10 = fmaxf(h10, 0.0f); h11 = fmaxf(h11, 0.0f);
            }
            char* p0 = smem + r * A_ROW_B + 512 + j * 2;
            char* p1 = p0 + 8 * A_ROW_B;
            *reinterpret_cast<uint32_t*>(p0)           = bf2_hi(h00, h01);
            *reinterpret_cast<uint32_t*>(p0 + ALO_OFF) = bf2_lo(h00, h01);
            *reinterpret_cast<uint32_t*>(p1)           = bf2_hi(h10, h11);
            *reinterpret_cast<uint32_t*>(p1 + ALO_OFF) = bf2_lo(h10, h11);
        }
    }
}

__global__ void __launch_bounds__(NTHR, 1)
rnn_fused_kernel(const float* __restrict__ X,
                 const float* __restrict__ lnw,
                 const float* __restrict__ lnb,
                 float* __restrict__ out) {
    extern __shared__ char smem[];
    uint32_t a_hi_u = (uint32_t)__cvta_generic_to_shared(smem);
    uint32_t* W_u32 = reinterpret_cast<uint32_t*>(smem + W_OFF);
    float* bias_s = reinterpret_cast<float*>(smem + BIAS_OFF);
    float* lnw_s  = bias_s + 256;
    float* lnb_s  = lnw_s + 256;

    const int tid  = threadIdx.x;
    const int lane = tid & 31;
    const int warp = tid >> 5;
    const int wm   = warp >> 2;     // 0..1  (32-row block)
    const int wn   = warp & 3;      // 0..3  (64-col block)
    const int row0 = blockIdx.x * RTILE;

    if (tid < 256) {
        bias_s[tid] = g_bias[tid];
        lnw_s[tid]  = lnw[tid];
        lnb_s[tid]  = lnb[tid];
    }
    __syncthreads();

    float lnw_r[8], lnb_r[8];
    #pragma unroll
    for (int jj = 0; jj < 8; ++jj) {
        lnw_r[jj] = lnw_s[lane * 8 + jj];
        lnb_r[jj] = lnb_s[lane * 8 + jj];
    }

    const int f4 = tid & 63;   // float4 column index (0..63)
    const int rb = tid >> 6;   // base row (0..3)

    float c[2][8][4];

    for (int t = 0; t < T_STEPS; ++t) {
        // ---- stage X_t -> A_hi/A_lo cols 0..255 ----
        const float* Xt = X + ((size_t)t * NROWS + row0) * 256;
        #pragma unroll
        for (int i = 0; i < 16; ++i) {
            int r = rb + i * 4;
            float4 v = *reinterpret_cast<const float4*>(Xt + r * 256 + f4 * 4);
            uint2 hw, lw;
            hw.x = bf2_hi(v.x, v.y); hw.y = bf2_hi(v.z, v.w);
            lw.x = bf2_lo(v.x, v.y); lw.y = bf2_lo(v.z, v.w);
            char* p = smem + r * A_ROW_B + f4 * 8;
            *reinterpret_cast<uint2*>(p)           = hw;
            *reinterpret_cast<uint2*>(p + ALO_OFF) = lw;
        }

        #pragma unroll
        for (int mt = 0; mt < 2; ++mt)
            #pragma unroll
            for (int nt = 0; nt < 8; ++nt)
                #pragma unroll
                for (int q = 0; q < 4; ++q) c[mt][nt][q] = 0.0f;

        // ---- W pipeline prologue: chunk 0 -> buf 0 ----
        {
            const char* src = reinterpret_cast<const char*>(g_Wfrag);
            char* dst = smem + W_OFF;
            #pragma unroll
            for (int q = 0; q < 8; ++q) {
                int i4 = tid + (q << 8);
                cp16(dst + i4 * 16, src + i4 * 16);
            }
            CP_COMMIT();
        }

        #pragma unroll 1
        for (int chunk = 0; chunk < 16; ++chunk) {
            if (chunk < 15) {
                const char* src = reinterpret_cast<const char*>(g_Wfrag) + (chunk + 1) * 32768;
                char* dst = smem + W_OFF + ((chunk + 1) & 1) * 32768;
                #pragma unroll
                for (int q = 0; q < 8; ++q) {
                    int i4 = tid + (q << 8);
                    cp16(dst + i4 * 16, src + i4 * 16);
                }
                CP_COMMIT();
                CP_WAIT1();
            } else {
                CP_WAIT0();
            }
            __syncthreads();

            // ---- compute this k32 chunk ----
            {
                const uint32_t* Wb = W_u32 + ((chunk & 1) << 13);
                const int kbyte = chunk << 6;   // 32 bf16 cols * 2B
                #pragma unroll
                for (int kt = 0; kt < 2; ++kt) {
                    uint32_t ah[2][4], al[2][4];
                    #pragma unroll
                    for (int mt = 0; mt < 2; ++mt) {
                        int row = wm * 32 + mt * 16 + (lane & 15);
                        uint32_t ad = a_hi_u + row * A_ROW_B + kbyte + kt * 32
                                    + ((lane >> 4) << 4);
                        LDSM4(ah[mt], ad);
                        LDSM4(al[mt], ad + ALO_OFF);
                    }
                    const uint32_t* pb = Wb + (kt << 11) + (wn << 3) * 64 + (lane << 1);
                    #pragma unroll
                    for (int nt = 0; nt < 8; ++nt) {
                        uint32_t bh0 = pb[0],    bh1 = pb[1];
                        uint32_t bl0 = pb[4096], bl1 = pb[4097];
                        MMA16816(c[0][nt], ah[0], bh0, bh1);
                        MMA16816(c[1][nt], ah[1], bh0, bh1);
                        MMA16816(c[0][nt], ah[0], bl0, bl1);
                        MMA16816(c[1][nt], ah[1], bl0, bl1);
                        MMA16816(c[0][nt], al[0], bh0, bh1);
                        MMA16816(c[1][nt], al[1], bh0, bh1);
                        pb += 64;
                    }
                }
            }
            __syncthreads();

            // t==0: after the X half, seed h0 = Xw0 + b_ih + b_hh (no relu)
            if (t == 0 && chunk == 7) {
                epi_store(c, bias_s, smem, wm, wn, lane, false);
                __syncthreads();
            }
        }

        // ---- h_new = relu(C + bias) -> A cols 256..511 (next step + LN source) ----
        epi_store(c, bias_s, smem, wm, wn, lane, true);
        __syncthreads();

        // ---- LayerNorm + coalesced output (warp-per-row) ----
        float* outT = out + ((size_t)t * NROWS + row0) * 256;
        #pragma unroll 1
        for (int i = 0; i < 8; ++i) {
            int r = warp * 8 + i;
            const char* ph = smem + r * A_ROW_B + 512 + lane * 16;
            uint4 hw = *reinterpret_cast<const uint4*>(ph);
            uint4 lw = *reinterpret_cast<const uint4*>(ph + ALO_OFF);
            float v[8];
            { float2 u = unp_add(hw.x, lw.x); v[0] = u.x; v[1] = u.y; }
            { float2 u = unp_add(hw.y, lw.y); v[2] = u.x; v[3] = u.y; }
            { float2 u = unp_add(hw.z, lw.z); v[4] = u.x; v[5] = u.y; }
            { float2 u = unp_add(hw.w, lw.w); v[6] = u.x; v[7] = u.y; }
            float s = 0.0f, s2 = 0.0f;
            #pragma unroll
            for (int jj = 0; jj < 8; ++jj) { s += v[jj]; s2 += v[jj] * v[jj]; }
            #pragma unroll
            for (int o = 16; o > 0; o >>= 1) {
                s  += __shfl_xor_sync(0xffffffffu, s,  o);
                s2 += __shfl_xor_sync(0xffffffffu, s2, o);
            }
            float mean = s  * (1.0f / 256.0f);
            float var  = s2 * (1.0f / 256.0f) - mean * mean;
            float rstd = rsqrtf(var + 1e-5f);
            float o8[8];
            #pragma unroll
            for (int jj = 0; jj < 8; ++jj)
                o8[jj] = (v[jj] - mean) * rstd * lnw_r[jj] + lnb_r[jj];
            float4 w0 = make_float4(o8[0], o8[1], o8[2], o8[3]);
            float4 w1 = make_float4(o8[4], o8[5], o8[6], o8[7]);
            *reinterpret_cast<float4*>(outT + r * 256 + lane * 8)     = w0;
            *reinterpret_cast<float4*>(outT + r * 256 + lane * 8 + 4) = w1;
        }
        // Next step's X staging touches A cols 0..255 only (disjoint from LN reads);
        // chunk-0 compute is fenced by the in-loop barrier.
    }
}

extern "C" void kernel_launch(void* const* d_in, const int* in_sizes, int n_in,
                              void* d_out, int out_size) {
    const float* X    = (const float*)d_in[0];
    const float* W_ih = (const float*)d_in[1];
    const float* W_hh = (const float*)d_in[2];
    const float* b_ih = (const float*)d_in[3];
    const float* b_hh = (const float*)d_in[4];
    const float* lnw  = (const float*)d_in[5];
    const float* lnb  = (const float*)d_in[6];
    float* out = (float*)d_out;

    (void)in_sizes; (void)n_in; (void)out_size;

    prep_kernel<<<256, 256>>>(W_ih, W_hh, b_ih, b_hh);

    cudaFuncSetAttribute(rnn_fused_kernel,
                         cudaFuncAttributeMaxDynamicSharedMemorySize, SMEM_BYTES);
    rnn_fused_kernel<<<NCTA, NTHR, SMEM_BYTES>>>(X, lnw, lnb, out);
}